// round 14
// baseline (speedup 1.0000x reference)
#include <cuda_runtime.h>

typedef unsigned long long u64;

__device__ __forceinline__ void fma2(u64& d, u64 a, u64 b) {
    asm("fma.rn.f32x2 %0, %1, %2, %0;" : "+l"(d) : "l"(a), "l"(b));
}

// Separable tap-set fold, fully unrolled, compile-time indices only.
// T(0)={1,2}, T(1)={0,1,2}, T(2)={0}  (from z = 2i-1+k, z-offset in [0,3])
__device__ __forceinline__ void fold27(const float* __restrict__ a, float sc,
                                       float* __restrict__ o) {
    float c[27];
#pragma unroll
    for (int j = 0; j < 9; ++j) {
        float i0 = a[3 * j], i1 = a[3 * j + 1], i2 = a[3 * j + 2];
        float t = i1 + i2;
        c[3 * j + 0] = t; c[3 * j + 1] = t + i0; c[3 * j + 2] = i0;
    }
    float d[27];
#pragma unroll
    for (int kd = 0; kd < 3; ++kd)
#pragma unroll
        for (int rw = 0; rw < 3; ++rw) {
            float r0 = c[(3 * kd + 0) * 3 + rw];
            float r1 = c[(3 * kd + 1) * 3 + rw];
            float r2 = c[(3 * kd + 2) * 3 + rw];
            float t = r1 + r2;
            d[(kd * 3 + 0) * 3 + rw] = t;
            d[(kd * 3 + 1) * 3 + rw] = t + r0;
            d[(kd * 3 + 2) * 3 + rw] = r0;
        }
#pragma unroll
    for (int rh = 0; rh < 3; ++rh)
#pragma unroll
        for (int rw = 0; rw < 3; ++rw) {
            float r0 = d[(0 * 3 + rh) * 3 + rw];
            float r1 = d[(1 * 3 + rh) * 3 + rw];
            float r2 = d[(2 * 3 + rh) * 3 + rw];
            float t = r1 + r2;
            o[(0 * 3 + rh) * 3 + rw] = t * sc;
            o[(1 * 3 + rh) * 3 + rw] = (t + r0) * sc;
            o[(2 * 3 + rh) * 3 + rw] = r0 * sc;
        }
}

// ---------------------------------------------------------------------------
// Single fused kernel. 296 blocks x 256 threads, 2 blocks/SM.
// Weights in SMEM (per-block copy) -> ~100 regs/thread so ptxas can hoist
// x loads; x read in half-row register batches; weights prefetched one row
// ahead; ONE __syncthreads per tile (red + xs double-buffered; all cross-
// iteration reuses are separated by at least one barrier).
// Block bid does tiles bid + it*296, it < nt (nt=4 for bid<80 else 3).
// Warp wid = ci pair; lane = co; fma.rn.f32x2 over 11 ow accumulators.
// ---------------------------------------------------------------------------
__global__ __launch_bounds__(256, 2)
void conv_fused_kernel(const float* __restrict__ x,
                       const float* __restrict__ wsrc,
                       const float* __restrict__ bias,
                       const float* __restrict__ gamma,
                       const float* __restrict__ beta,
                       const float* __restrict__ mean,
                       const float* __restrict__ var,
                       float* __restrict__ out) {
    extern __shared__ __align__(16) char sm[];
    u64*   wsm = reinterpret_cast<u64*>(sm);             // 8*27*32 u64 = 55296 B
    u64*   xs  = reinterpret_cast<u64*>(sm + 55296);     // 2*1728 u64  = 27648 B
    float* red = reinterpret_cast<float*>(sm + 82944);   // 2*8*352 f   = 22528 B

    const int tid  = threadIdx.x;
    const int lane = tid & 31;   // co
    const int wid  = tid >> 5;   // ci pair
    const int bid  = blockIdx.x;

    const float scale = __ldg(&gamma[lane]) * rsqrtf(__ldg(&var[lane]) + 1e-5f);
    const float cb = __ldg(&bias[lane]) * scale + __ldg(&beta[lane])
                   - __ldg(&mean[lane]) * scale;
    const float sc64 = scale * (1.f / 64.f);

    // ====== in-kernel weight fold (all 8 warps; xs area as scratch) ======
    {
        float* scr = reinterpret_cast<float*>(xs) + wid * 864;   // 3456 B/warp
        float* wb = reinterpret_cast<float*>(wsm) + (wid * 27 * 32 + lane) * 2;
#pragma unroll 1
        for (int ph = 0; ph < 2; ++ph) {   // ci = 2*wid + ph
            const float4* src = reinterpret_cast<const float4*>(
                wsrc + (size_t)(2 * wid + ph) * 864);
            float4* dst = reinterpret_cast<float4*>(scr);
#pragma unroll
            for (int k = 0; k < 7; ++k) {
                int i = lane + k * 32;
                if (i < 216) dst[i] = __ldg(src + i);
            }
            __syncwarp();
            float a[27];
            const float* ap = scr + lane * 27;   // stride 27 vs 32 banks: clean
#pragma unroll
            for (int k = 0; k < 27; ++k) a[k] = ap[k];
            float o[27];
            fold27(a, sc64, o);
#pragma unroll
            for (int r = 0; r < 27; ++r) wb[r * 64 + ph] = o[r];
            __syncwarp();
        }
    }

    // ====== staging task decode (hoisted; 432 tasks per tile) ======
    const int p0  = tid / 54, u0 = tid - p0 * 54;
    const int rr0 = u0 / 6,  q0 = u0 - rr0 * 6;
    const int so0 = 2 * p0 * 13824 + (rr0 / 3) * 576 + (rr0 % 3) * 24 + 4 * q0;
    const int df0 = (p0 * 9 + rr0) * 12 + 2 * q0;      // float4 index in xs buf

    const bool h1 = (tid < 176);
    const int t1  = tid + 256;
    const int p1  = t1 / 54, u1 = t1 - p1 * 54;
    const int rr1 = u1 / 6,  q1 = u1 - rr1 * 6;
    const int so1 = 2 * p1 * 13824 + (rr1 / 3) * 576 + (rr1 % 3) * 24 + 4 * q1;
    const int df1 = (p1 * 9 + rr1) * 12 + 2 * q1;

    const int nt = (bid < 80) ? 4 : 3;   // 80*4 + 216*3 = 968 tiles

    // ====== prologue: stage tile 0 (fold scratch -> must sync first) ======
    {
        int b = bid / 121, rem = bid - b * 121;
        const float* xb = x + (size_t)b * 221184 + 2 * (rem / 11) * 576 + 2 * (rem % 11) * 24;
        float4 A0 = __ldg(reinterpret_cast<const float4*>(xb + so0));
        float4 B0 = __ldg(reinterpret_cast<const float4*>(xb + so0 + 13824));
        float4 A1, B1;
        if (h1) {
            A1 = __ldg(reinterpret_cast<const float4*>(xb + so1));
            B1 = __ldg(reinterpret_cast<const float4*>(xb + so1 + 13824));
        }
        __syncthreads();   // fold scratch reads done everywhere
        float4* d = reinterpret_cast<float4*>(xs);
        d[df0]     = make_float4(A0.x, B0.x, A0.y, B0.y);
        d[df0 + 1] = make_float4(A0.z, B0.z, A0.w, B0.w);
        if (h1) {
            d[df1]     = make_float4(A1.x, B1.x, A1.y, B1.y);
            d[df1 + 1] = make_float4(A1.z, B1.z, A1.w, B1.w);
        }
    }
    __syncthreads();

    // ====== main loop: ONE barrier per tile ======
#pragma unroll 1
    for (int it = 0; it < nt; ++it) {
        const int gw = bid + it * 296;
        const int b = gw / 121, rem = gw - b * 121;
        const int od = rem / 11, oh = rem - od * 11;

        // issue next tile's global loads (hidden under compute)
        const bool more = (it + 1) < nt;
        float4 A0, B0, A1, B1;
        if (more) {
            int gn = gw + 296;
            int bn = gn / 121, rn = gn - bn * 121;
            const float* xb = x + (size_t)bn * 221184 + 2 * (rn / 11) * 576 + 2 * (rn % 11) * 24;
            A0 = __ldg(reinterpret_cast<const float4*>(xb + so0));
            B0 = __ldg(reinterpret_cast<const float4*>(xb + so0 + 13824));
            if (h1) {
                A1 = __ldg(reinterpret_cast<const float4*>(xb + so1));
                B1 = __ldg(reinterpret_cast<const float4*>(xb + so1 + 13824));
            }
        }

        // ---- compute: weights prefetched a row ahead, x in half-row batches
        const u64* xw = xs + (it & 1) * 1728 + wid * 216;
        const u64* wp = wsm + wid * 864 + lane;
        u64 acc[11];
#pragma unroll
        for (int i = 0; i < 11; ++i) acc[i] = 0ull;

        u64 wc0 = wp[0], wc1 = wp[32], wc2 = wp[64];
#pragma unroll
        for (int rr = 0; rr < 9; ++rr) {
            u64 wn0, wn1, wn2;
            if (rr < 8) {   // prefetch next row's weights
                wn0 = wp[(3 * rr + 3) * 32];
                wn1 = wp[(3 * rr + 4) * 32];
                wn2 = wp[(3 * rr + 5) * 32];
            }
            const ulonglong2* rp = reinterpret_cast<const ulonglong2*>(xw + rr * 24);

            // half 1: x positions 0..13 (7 hoisted LDS.128)
            u64 xv[14];
#pragma unroll
            for (int k = 0; k < 7; ++k) {
                ulonglong2 t = rp[k];
                xv[2 * k] = t.x; xv[2 * k + 1] = t.y;
            }
#pragma unroll
            for (int ow = 0; ow < 6; ++ow) {
                fma2(acc[ow], wc0, xv[2 * ow]);
                fma2(acc[ow], wc1, xv[2 * ow + 1]);
                fma2(acc[ow], wc2, xv[2 * ow + 2]);
            }
            // half 2: x positions 14..23 (5 hoisted LDS.128)
            u64 xu[10];
#pragma unroll
            for (int k = 0; k < 5; ++k) {
                ulonglong2 t = rp[7 + k];
                xu[2 * k] = t.x; xu[2 * k + 1] = t.y;
            }
            fma2(acc[6], wc0, xv[12]);
            fma2(acc[6], wc1, xv[13]);
            fma2(acc[6], wc2, xu[0]);
#pragma unroll
            for (int ow = 7; ow < 11; ++ow) {
                fma2(acc[ow], wc0, xu[2 * ow - 14]);
                fma2(acc[ow], wc1, xu[2 * ow - 13]);
                fma2(acc[ow], wc2, xu[2 * ow - 12]);
            }
            wc0 = wn0; wc1 = wn1; wc2 = wn2;
        }

        // ---- write partials to this tile's red buffer
        float* redc = red + (it & 1) * 2816 + wid * 352;
#pragma unroll
        for (int ow = 0; ow < 11; ++ow) {
            float lo, hi;
            asm("mov.b64 {%0, %1}, %2;" : "=f"(lo), "=f"(hi) : "l"(acc[ow]));
            redc[ow * 32 + lane] = lo + hi;
        }

        // ---- stage next tile's x into the other xs buffer
        if (more) {
            float4* d = reinterpret_cast<float4*>(xs + ((it + 1) & 1) * 1728);
            d[df0]     = make_float4(A0.x, B0.x, A0.y, B0.y);
            d[df0 + 1] = make_float4(A0.z, B0.z, A0.w, B0.w);
            if (h1) {
                d[df1]     = make_float4(A1.x, B1.x, A1.y, B1.y);
                d[df1 + 1] = make_float4(A1.z, B1.z, A1.w, B1.w);
            }
        }

        __syncthreads();   // red[it&1] + xs[(it+1)&1] visible; xs[it&1] reads done

        // ---- store this tile (overlaps next iteration's compute)
        {
            const float* rb = red + (it & 1) * 2816;
            if (tid < 96) {
                int j = tid + 256;
                float s1 = cb;
#pragma unroll
                for (int w = 0; w < 8; ++w) s1 += rb[w * 352 + j];
                out[((size_t)(b * 32 + lane)) * 1331 + od * 121 + oh * 11 + (j >> 5)] = s1;
            }
            float s0 = cb;
            int j0 = (tid < 352) ? tid : 0;
#pragma unroll
            for (int w = 0; w < 8; ++w) s0 += rb[w * 352 + j0];
            if (tid < 352)
                out[((size_t)(b * 32 + lane)) * 1331 + od * 121 + oh * 11 + (tid >> 5)] = s0;
        }
    }
}

extern "C" void kernel_launch(void* const* d_in, const int* in_sizes, int n_in,
                              void* d_out, int out_size) {
    const float* x     = (const float*)d_in[0];
    const float* w     = (const float*)d_in[1];
    const float* bias  = (const float*)d_in[2];
    const float* gamma = (const float*)d_in[3];
    const float* beta  = (const float*)d_in[4];
    const float* mean  = (const float*)d_in[5];
    const float* var   = (const float*)d_in[6];
    float* out = (float*)d_out;

    cudaFuncSetAttribute(conv_fused_kernel,
                         cudaFuncAttributeMaxDynamicSharedMemorySize, 105472);
    conv_fused_kernel<<<296, 256, 105472>>>(x, w, bias, gamma, beta, mean, var, out);
}

// round 15
// speedup vs baseline: 1.0135x; 1.0135x over previous
#include <cuda_runtime.h>

typedef unsigned long long u64;

__device__ __forceinline__ void fma2(u64& d, u64 a, u64 b) {
    asm("fma.rn.f32x2 %0, %1, %2, %0;" : "+l"(d) : "l"(a), "l"(b));
}

// Separable tap-set fold, fully unrolled, compile-time indices only.
// T(0)={1,2}, T(1)={0,1,2}, T(2)={0}  (from z = 2i-1+k, z-offset in [0,3])
__device__ __forceinline__ void fold27(const float* __restrict__ a, float sc,
                                       float* __restrict__ o) {
    float c[27];
#pragma unroll
    for (int j = 0; j < 9; ++j) {
        float i0 = a[3 * j], i1 = a[3 * j + 1], i2 = a[3 * j + 2];
        float t = i1 + i2;
        c[3 * j + 0] = t; c[3 * j + 1] = t + i0; c[3 * j + 2] = i0;
    }
    float d[27];
#pragma unroll
    for (int kd = 0; kd < 3; ++kd)
#pragma unroll
        for (int rw = 0; rw < 3; ++rw) {
            float r0 = c[(3 * kd + 0) * 3 + rw];
            float r1 = c[(3 * kd + 1) * 3 + rw];
            float r2 = c[(3 * kd + 2) * 3 + rw];
            float t = r1 + r2;
            d[(kd * 3 + 0) * 3 + rw] = t;
            d[(kd * 3 + 1) * 3 + rw] = t + r0;
            d[(kd * 3 + 2) * 3 + rw] = r0;
        }
#pragma unroll
    for (int rh = 0; rh < 3; ++rh)
#pragma unroll
        for (int rw = 0; rw < 3; ++rw) {
            float r0 = d[(0 * 3 + rh) * 3 + rw];
            float r1 = d[(1 * 3 + rh) * 3 + rw];
            float r2 = d[(2 * 3 + rh) * 3 + rw];
            float t = r1 + r2;
            o[(0 * 3 + rh) * 3 + rw] = t * sc;
            o[(1 * 3 + rh) * 3 + rw] = (t + r0) * sc;
            o[(2 * 3 + rh) * 3 + rw] = r0 * sc;
        }
}

// ---------------------------------------------------------------------------
// Single fused kernel. 152 persistent blocks x 768 threads, 1 block/SM.
// 24 warps/block: warp = (ci-pair p = wid&7, rd-plane d = wid>>3).
// Per-warp per tile: 9 lane-strided weight LDS.64 + 36 broadcast x LDS.128
// + 99 fma.rn.f32x2 into 11 ow accumulators. ~75 regs/thread so the RF
// admits all 768 threads (24 warps/SM = +50% latency cover vs 16).
// x staged ci-pair-interleaved, double-buffered; ONE staging task per thread
// (432 < 768); next tile's LDGs issue before compute. 24-way reduction via
// smem; 2 barriers per tile. Block bid does tiles bid + it*152 (7 for
// bid<56 else 6; 56*7 + 96*6 = 968).
// ---------------------------------------------------------------------------
__global__ __launch_bounds__(768, 1)
void conv_fused_kernel(const float* __restrict__ x,
                       const float* __restrict__ wsrc,
                       const float* __restrict__ bias,
                       const float* __restrict__ gamma,
                       const float* __restrict__ beta,
                       const float* __restrict__ mean,
                       const float* __restrict__ var,
                       float* __restrict__ out) {
    extern __shared__ __align__(16) char sm[];
    u64*   wsm = reinterpret_cast<u64*>(sm);             // 8*27*32 u64 = 55296 B
    u64*   xs  = reinterpret_cast<u64*>(sm + 55296);     // 2*1728 u64  = 27648 B
    float* red = reinterpret_cast<float*>(sm + 82944);   // 24*352 f    = 33792 B

    const int tid  = threadIdx.x;
    const int lane = tid & 31;   // co
    const int wid  = tid >> 5;   // 0..23
    const int bid  = blockIdx.x;

    const float scale = __ldg(&gamma[lane]) * rsqrtf(__ldg(&var[lane]) + 1e-5f);
    const float cb = __ldg(&bias[lane]) * scale + __ldg(&beta[lane])
                   - __ldg(&mean[lane]) * scale;
    const float sc64 = scale * (1.f / 64.f);

    // ====== in-kernel weight fold (warps 0-7; xs region as scratch) ======
    if (wid < 8) {
        float* scr = reinterpret_cast<float*>(xs) + wid * 864;   // 3456 B/warp
        float* wb = reinterpret_cast<float*>(wsm) + (wid * 27 * 32 + lane) * 2;
#pragma unroll 1
        for (int ph = 0; ph < 2; ++ph) {   // ci = 2*wid + ph
            const float4* src = reinterpret_cast<const float4*>(
                wsrc + (size_t)(2 * wid + ph) * 864);
            float4* dst = reinterpret_cast<float4*>(scr);
#pragma unroll
            for (int k = 0; k < 7; ++k) {
                int i = lane + k * 32;
                if (i < 216) dst[i] = __ldg(src + i);
            }
            __syncwarp();
            float a[27];
            const float* ap = scr + lane * 27;   // stride 27 vs 32 banks: clean
#pragma unroll
            for (int k = 0; k < 27; ++k) a[k] = ap[k];
            float o[27];
            fold27(a, sc64, o);
#pragma unroll
            for (int r = 0; r < 27; ++r) wb[r * 64 + ph] = o[r];
            __syncwarp();
        }
    }
    __syncthreads();   // wsm ready; xs scratch free

    // ====== staging decode: ONE task per thread (tid < 432) ======
    const bool stv = tid < 432;
    const int p0  = tid / 54, u0 = tid - p0 * 54;
    const int rr0 = u0 / 6,  q0 = u0 - rr0 * 6;
    const int so0 = 2 * p0 * 13824 + (rr0 / 3) * 576 + (rr0 % 3) * 24 + 4 * q0;
    const int df0 = (p0 * 9 + rr0) * 12 + 2 * q0;      // float4 index in xs buf

    const int nt = (bid < 56) ? 7 : 6;   // 56*7 + 96*6 = 968 tiles

    // ====== prologue: stage tile 0 ======
    if (stv) {
        int b = bid / 121, rem = bid - b * 121;
        const float* xb = x + (size_t)b * 221184 + 2 * (rem / 11) * 576 + 2 * (rem % 11) * 24;
        float4 A = __ldg(reinterpret_cast<const float4*>(xb + so0));
        float4 B = __ldg(reinterpret_cast<const float4*>(xb + so0 + 13824));
        float4* d = reinterpret_cast<float4*>(xs);
        d[df0]     = make_float4(A.x, B.x, A.y, B.y);
        d[df0 + 1] = make_float4(A.z, B.z, A.w, B.w);
    }
    __syncthreads();

    const int pd = wid & 7;    // ci pair
    const int dd = wid >> 3;   // rd plane
    const u64* wpw = wsm + ((size_t)pd * 27 + dd * 9) * 32 + lane;

    // ====== main loop ======
#pragma unroll 1
    for (int it = 0; it < nt; ++it) {
        const int gw = bid + it * 152;
        const int b = gw / 121, rem = gw - b * 121;
        const int od = rem / 11, oh = rem - od * 11;

        // issue next tile's global loads (hidden under compute)
        const bool more = (it + 1) < nt;
        float4 A, B;
        if (more && stv) {
            int gn = gw + 152;
            int bn = gn / 121, rn = gn - bn * 121;
            const float* xb = x + (size_t)bn * 221184 + 2 * (rn / 11) * 576 + 2 * (rn % 11) * 24;
            A = __ldg(reinterpret_cast<const float4*>(xb + so0));
            B = __ldg(reinterpret_cast<const float4*>(xb + so0 + 13824));
        }

        // ---- compute: this warp's rd-plane (3 rh rows) for its ci pair ----
        u64 acc[11];
#pragma unroll
        for (int i = 0; i < 11; ++i) acc[i] = 0ull;
        const u64* xw = xs + (it & 1) * 1728 + (pd * 9 + dd * 3) * 24;

#pragma unroll
        for (int rh = 0; rh < 3; ++rh) {
            u64 w0 = wpw[(rh * 3 + 0) * 32];
            u64 w1 = wpw[(rh * 3 + 1) * 32];
            u64 w2 = wpw[(rh * 3 + 2) * 32];
            const ulonglong2* rp = reinterpret_cast<const ulonglong2*>(xw + rh * 24);

            u64 xv[14];
#pragma unroll
            for (int k = 0; k < 7; ++k) {
                ulonglong2 t = rp[k];
                xv[2 * k] = t.x; xv[2 * k + 1] = t.y;
            }
#pragma unroll
            for (int ow = 0; ow < 6; ++ow) {
                fma2(acc[ow], w0, xv[2 * ow]);
                fma2(acc[ow], w1, xv[2 * ow + 1]);
                fma2(acc[ow], w2, xv[2 * ow + 2]);
            }
            u64 xu[10];
#pragma unroll
            for (int k = 0; k < 5; ++k) {
                ulonglong2 t = rp[7 + k];
                xu[2 * k] = t.x; xu[2 * k + 1] = t.y;
            }
            fma2(acc[6], w0, xv[12]);
            fma2(acc[6], w1, xv[13]);
            fma2(acc[6], w2, xu[0]);
#pragma unroll
            for (int ow = 7; ow < 11; ++ow) {
                fma2(acc[ow], w0, xu[2 * ow - 14]);
                fma2(acc[ow], w1, xu[2 * ow - 13]);
                fma2(acc[ow], w2, xu[2 * ow - 12]);
            }
        }

        // ---- write this warp's partials ----
        float* rw_ = red + wid * 352;
#pragma unroll
        for (int ow = 0; ow < 11; ++ow) {
            float lo, hi;
            asm("mov.b64 {%0, %1}, %2;" : "=f"(lo), "=f"(hi) : "l"(acc[ow]));
            rw_[ow * 32 + lane] = lo + hi;
        }

        // ---- stage next tile into the other xs buffer ----
        if (more && stv) {
            float4* d = reinterpret_cast<float4*>(xs + ((it + 1) & 1) * 1728);
            d[df0]     = make_float4(A.x, B.x, A.y, B.y);
            d[df0 + 1] = make_float4(A.z, B.z, A.w, B.w);
        }
        __syncthreads();   // red + new xs visible; old xs reads done

        // ---- 24-way reduce + store (coalesced: consecutive tid = consecutive j)
        if (tid < 352) {
            float s = cb;
#pragma unroll
            for (int w = 0; w < 24; ++w) s += red[w * 352 + tid];
            out[((size_t)(b * 32 + lane)) * 1331 + od * 121 + oh * 11 + (tid >> 5)] = s;
        }
        __syncthreads();   // red reads done before next tile's writes
    }
}

extern "C" void kernel_launch(void* const* d_in, const int* in_sizes, int n_in,
                              void* d_out, int out_size) {
    const float* x     = (const float*)d_in[0];
    const float* w     = (const float*)d_in[1];
    const float* bias  = (const float*)d_in[2];
    const float* gamma = (const float*)d_in[3];
    const float* beta  = (const float*)d_in[4];
    const float* mean  = (const float*)d_in[5];
    const float* var   = (const float*)d_in[6];
    float* out = (float*)d_out;

    cudaFuncSetAttribute(conv_fused_kernel,
                         cudaFuncAttributeMaxDynamicSharedMemorySize, 116736);
    conv_fused_kernel<<<152, 768, 116736>>>(x, w, bias, gamma, beta, mean, var, out);
}